// round 12
// baseline (speedup 1.0000x reference)
#include <cuda_runtime.h>
#include <cuda_bf16.h>
#include <math.h>
#include <stdint.h>

#define NHEADS 16
#define DKH 64
#define BATCH 2
#define SEQ 2048
#define DMODEL 1024
#define MTOT (BATCH * SEQ)      // 4096
#define BHTOT (BATCH * NHEADS)  // 32

// Scratch (__device__ globals: allocation-free)
__device__ float g_q[BHTOT * SEQ * DKH];
__device__ float g_k[BHTOT * SEQ * DKH];
__device__ float g_v[BHTOT * SEQ * DKH];
__device__ float g_attn[MTOT * DMODEL];

// ============================================================
// mma helpers (layouts HW-verified R4/R6/R9)
// ============================================================
__device__ __forceinline__ uint32_t f2tf32(float x) {
    uint32_t r;
    asm("cvt.rna.tf32.f32 %0, %1;" : "=r"(r) : "f"(x));
    return r;
}

__device__ __forceinline__ void mma_tf32(float d[4], const uint32_t a[4],
                                         const uint32_t b[2]) {
    asm volatile(
        "mma.sync.aligned.m16n8k8.row.col.f32.tf32.tf32.f32 "
        "{%0,%1,%2,%3}, {%4,%5,%6,%7}, {%8,%9}, {%0,%1,%2,%3};\n"
        : "+f"(d[0]), "+f"(d[1]), "+f"(d[2]), "+f"(d[3])
        : "r"(a[0]), "r"(a[1]), "r"(a[2]), "r"(a[3]), "r"(b[0]), "r"(b[1]));
}

__device__ __forceinline__ void mma_bf16(float d[4], const uint32_t a[4],
                                         const uint32_t b[2]) {
    asm volatile(
        "mma.sync.aligned.m16n8k16.row.col.f32.bf16.bf16.f32 "
        "{%0,%1,%2,%3}, {%4,%5,%6,%7}, {%8,%9}, {%0,%1,%2,%3};\n"
        : "+f"(d[0]), "+f"(d[1]), "+f"(d[2]), "+f"(d[3])
        : "r"(a[0]), "r"(a[1]), "r"(a[2]), "r"(a[3]), "r"(b[0]), "r"(b[1]));
}

__device__ __forceinline__ void cvt_hilo(float4 v, uint2& h, uint2& l) {
    __nv_bfloat16 h0 = __float2bfloat16_rn(v.x);
    __nv_bfloat16 h1 = __float2bfloat16_rn(v.y);
    __nv_bfloat16 h2 = __float2bfloat16_rn(v.z);
    __nv_bfloat16 h3 = __float2bfloat16_rn(v.w);
    __nv_bfloat16 l0 = __float2bfloat16_rn(v.x - __bfloat162float(h0));
    __nv_bfloat16 l1 = __float2bfloat16_rn(v.y - __bfloat162float(h1));
    __nv_bfloat16 l2 = __float2bfloat16_rn(v.z - __bfloat162float(h2));
    __nv_bfloat16 l3 = __float2bfloat16_rn(v.w - __bfloat162float(h3));
    __nv_bfloat162 hp0 = __halves2bfloat162(h0, h1);
    __nv_bfloat162 hp1 = __halves2bfloat162(h2, h3);
    __nv_bfloat162 lp0 = __halves2bfloat162(l0, l1);
    __nv_bfloat162 lp1 = __halves2bfloat162(l2, l3);
    h.x = *(uint32_t*)&hp0;
    h.y = *(uint32_t*)&hp1;
    l.x = *(uint32_t*)&lp0;
    l.y = *(uint32_t*)&lp1;
}

// ============================================================
// BF16x3 tensor-core GEMM for Q AND K projections, fused:
// grid.z = 0 -> (wq, g_q), 1 -> (wk, g_k). Split-heads epilogue.
// ============================================================
#define BP 12

__global__ __launch_bounds__(256, 2) void qk3_gemm(const float* __restrict__ Ain,
                                                   const float* __restrict__ Wq,
                                                   const float* __restrict__ Wk) {
    __shared__ __align__(16) uint32_t Ah[128 * BP];
    __shared__ __align__(16) uint32_t Al[128 * BP];
    __shared__ __align__(16) uint32_t Bh[128 * BP];
    __shared__ __align__(16) uint32_t Bl[128 * BP];

    const float* Bw = (blockIdx.z == 0) ? Wq : Wk;
    const int K = 1024;
    const int tid = threadIdx.x;
    const int lane = tid & 31, warp = tid >> 5;
    const int wm = warp >> 2, wn = warp & 3;
    const int g = lane >> 2, t = lane & 3;
    const int bm = blockIdx.y, bn = blockIdx.x;

    const int lm = tid >> 2;
    const int kw = (tid & 3) * 2;
    const int k4 = (tid & 3) * 4;

    const float* Ap = Ain + (size_t)(bm * 128 + lm) * K + k4;
    const float* Bp = Bw + (size_t)(bn * 128 + lm) * K + k4;

    float d[4][4][4];
#pragma unroll
    for (int i = 0; i < 4; i++)
#pragma unroll
        for (int j = 0; j < 4; j++)
#pragma unroll
            for (int c = 0; c < 4; c++) d[i][j][c] = 0.0f;

    float4 a0v = *(const float4*)(Ap);
    float4 a1v = *(const float4*)(Ap + 64 * K);
    float4 b0v = *(const float4*)(Bp);
    float4 b1v = *(const float4*)(Bp + 64 * K);

    for (int k0 = 0; k0 < K; k0 += 16) {
        uint2 h, l;
        cvt_hilo(a0v, h, l);
        *(uint2*)&Ah[lm * BP + kw] = h;
        *(uint2*)&Al[lm * BP + kw] = l;
        cvt_hilo(a1v, h, l);
        *(uint2*)&Ah[(lm + 64) * BP + kw] = h;
        *(uint2*)&Al[(lm + 64) * BP + kw] = l;
        cvt_hilo(b0v, h, l);
        *(uint2*)&Bh[lm * BP + kw] = h;
        *(uint2*)&Bl[lm * BP + kw] = l;
        cvt_hilo(b1v, h, l);
        *(uint2*)&Bh[(lm + 64) * BP + kw] = h;
        *(uint2*)&Bl[(lm + 64) * BP + kw] = l;
        __syncthreads();

        if (k0 + 16 < K) {
            a0v = *(const float4*)(Ap + k0 + 16);
            a1v = *(const float4*)(Ap + 64 * K + k0 + 16);
            b0v = *(const float4*)(Bp + k0 + 16);
            b1v = *(const float4*)(Bp + 64 * K + k0 + 16);
        }

        uint32_t afh[4][4], bfh[4][2];
#pragma unroll
        for (int mt = 0; mt < 4; mt++) {
            const int mb = wm * 64 + mt * 16 + g;
            afh[mt][0] = Ah[mb * BP + t];
            afh[mt][1] = Ah[(mb + 8) * BP + t];
            afh[mt][2] = Ah[mb * BP + t + 4];
            afh[mt][3] = Ah[(mb + 8) * BP + t + 4];
        }
#pragma unroll
        for (int nt = 0; nt < 4; nt++) {
            const int nb = wn * 32 + nt * 8 + g;
            bfh[nt][0] = Bh[nb * BP + t];
            bfh[nt][1] = Bh[nb * BP + t + 4];
        }
#pragma unroll
        for (int mt = 0; mt < 4; mt++)
#pragma unroll
            for (int nt = 0; nt < 4; nt++) mma_bf16(d[mt][nt], afh[mt], bfh[nt]);
        {
            uint32_t afl[4][4];
#pragma unroll
            for (int mt = 0; mt < 4; mt++) {
                const int mb = wm * 64 + mt * 16 + g;
                afl[mt][0] = Al[mb * BP + t];
                afl[mt][1] = Al[(mb + 8) * BP + t];
                afl[mt][2] = Al[mb * BP + t + 4];
                afl[mt][3] = Al[(mb + 8) * BP + t + 4];
            }
#pragma unroll
            for (int mt = 0; mt < 4; mt++)
#pragma unroll
                for (int nt = 0; nt < 4; nt++) mma_bf16(d[mt][nt], afl[mt], bfh[nt]);
        }
        {
            uint32_t bfl[4][2];
#pragma unroll
            for (int nt = 0; nt < 4; nt++) {
                const int nb = wn * 32 + nt * 8 + g;
                bfl[nt][0] = Bl[nb * BP + t];
                bfl[nt][1] = Bl[nb * BP + t + 4];
            }
#pragma unroll
            for (int mt = 0; mt < 4; mt++)
#pragma unroll
                for (int nt = 0; nt < 4; nt++) mma_bf16(d[mt][nt], afh[mt], bfl[nt]);
        }
        __syncthreads();
    }

    float* C = (blockIdx.z == 0) ? g_q : g_k;
#pragma unroll
    for (int mt = 0; mt < 4; mt++) {
#pragma unroll
        for (int nt = 0; nt < 4; nt++) {
            const int m0 = bm * 128 + wm * 64 + mt * 16 + g;
            const int n0 = bn * 128 + wn * 32 + nt * 8 + 2 * t;
#pragma unroll
            for (int half = 0; half < 2; half++) {
                const int m = m0 + half * 8;
                const int bb = m >> 11, ll = m & 2047;
                const int hh = n0 >> 6, dk = n0 & 63;
                float2* p = (float2*)&C[(((size_t)(bb * 16 + hh) * 2048) + ll) * 64 + dk];
                *p = make_float2(d[mt][nt][half * 2 + 0], d[mt][nt][half * 2 + 1]);
            }
        }
    }
}

// ============================================================
// Plain TF32 tensor-core GEMM (V-proj / O-proj). Unchanged.
// ============================================================
#define TP 20

template <int DEST>
__global__ __launch_bounds__(256, 2) void tf32_gemm(const float* __restrict__ Ain,
                                                    const float* __restrict__ Bw,
                                                    float* __restrict__ Cout) {
    __shared__ __align__(16) uint32_t As[128 * TP];
    __shared__ __align__(16) uint32_t Bs[128 * TP];

    const float* A = (DEST == 3) ? (const float*)g_attn : Ain;
    const int K = 1024;
    const int tid = threadIdx.x;
    const int lane = tid & 31, warp = tid >> 5;
    const int wm = warp >> 2, wn = warp & 3;
    const int g = lane >> 2, t = lane & 3;
    const int bm = blockIdx.y, bn = blockIdx.x;

    const int lm = tid >> 2;
    const int k4 = (tid & 3) * 4;

    const float* Ap = A + (size_t)(bm * 128 + lm) * K + k4;
    const float* Bp = Bw + (size_t)(bn * 128 + lm) * K + k4;

    float d[4][4][4];
#pragma unroll
    for (int i = 0; i < 4; i++)
#pragma unroll
        for (int j = 0; j < 4; j++)
#pragma unroll
            for (int c = 0; c < 4; c++) d[i][j][c] = 0.0f;

    float4 a0v = *(const float4*)(Ap);
    float4 a1v = *(const float4*)(Ap + 64 * K);
    float4 b0v = *(const float4*)(Bp);
    float4 b1v = *(const float4*)(Bp + 64 * K);

    for (int k0 = 0; k0 < K; k0 += 16) {
        uint4 s;
        s.x = f2tf32(a0v.x); s.y = f2tf32(a0v.y); s.z = f2tf32(a0v.z); s.w = f2tf32(a0v.w);
        *(uint4*)&As[lm * TP + k4] = s;
        s.x = f2tf32(a1v.x); s.y = f2tf32(a1v.y); s.z = f2tf32(a1v.z); s.w = f2tf32(a1v.w);
        *(uint4*)&As[(lm + 64) * TP + k4] = s;
        s.x = f2tf32(b0v.x); s.y = f2tf32(b0v.y); s.z = f2tf32(b0v.z); s.w = f2tf32(b0v.w);
        *(uint4*)&Bs[lm * TP + k4] = s;
        s.x = f2tf32(b1v.x); s.y = f2tf32(b1v.y); s.z = f2tf32(b1v.z); s.w = f2tf32(b1v.w);
        *(uint4*)&Bs[(lm + 64) * TP + k4] = s;
        __syncthreads();

        if (k0 + 16 < K) {
            a0v = *(const float4*)(Ap + k0 + 16);
            a1v = *(const float4*)(Ap + 64 * K + k0 + 16);
            b0v = *(const float4*)(Bp + k0 + 16);
            b1v = *(const float4*)(Bp + 64 * K + k0 + 16);
        }

#pragma unroll
        for (int ks = 0; ks < 16; ks += 8) {
            uint32_t af[4][4], bf[4][2];
#pragma unroll
            for (int mt = 0; mt < 4; mt++) {
                const int mb = wm * 64 + mt * 16 + g;
                af[mt][0] = As[mb * TP + ks + t];
                af[mt][1] = As[(mb + 8) * TP + ks + t];
                af[mt][2] = As[mb * TP + ks + t + 4];
                af[mt][3] = As[(mb + 8) * TP + ks + t + 4];
            }
#pragma unroll
            for (int nt = 0; nt < 4; nt++) {
                const int nb = wn * 32 + nt * 8 + g;
                bf[nt][0] = Bs[nb * TP + ks + t];
                bf[nt][1] = Bs[nb * TP + ks + t + 4];
            }
#pragma unroll
            for (int mt = 0; mt < 4; mt++)
#pragma unroll
                for (int nt = 0; nt < 4; nt++) mma_tf32(d[mt][nt], af[mt], bf[nt]);
        }
        __syncthreads();
    }

#pragma unroll
    for (int mt = 0; mt < 4; mt++) {
#pragma unroll
        for (int nt = 0; nt < 4; nt++) {
            const int m0 = bm * 128 + wm * 64 + mt * 16 + g;
            const int n0 = bn * 128 + wn * 32 + nt * 8 + 2 * t;
#pragma unroll
            for (int half = 0; half < 2; half++) {
                const int m = m0 + half * 8;
                const float v0 = d[mt][nt][half * 2 + 0];
                const float v1 = d[mt][nt][half * 2 + 1];
                if (DEST == 3) {
                    float2* p = (float2*)&Cout[(size_t)m * 1024 + n0];
                    *p = make_float2(v0, v1);
                } else {
                    const int bb = m >> 11, ll = m & 2047;
                    const int hh = n0 >> 6, dk = n0 & 63;
                    float2* p = (float2*)&g_v[(((size_t)(bb * 16 + hh) * 2048) + ll) * 64 + dk];
                    *p = make_float2(v0, v1);
                }
            }
        }
    }
}

// ============================================================
// Tensor-core causal flash attention (tf32 mma, fp32 softmax).
// R12: BR=128 (32 Q rows/warp, 2 mma row-blocks). K and V
// b-fragments loaded once per tile per warp feed BOTH row-blocks
// -> per-unit-work fragment LDS traffic halves. Single-buffered
// (double-buffer was neutral). Smem 36.3KB static.
// ============================================================
#define QPT 68
#define VPT 72
#define PPT 36

__global__ __launch_bounds__(128) void flash_attn_tc() {
    __shared__ __align__(16) uint32_t Ks[32 * QPT];   //  8704 B
    __shared__ __align__(16) uint32_t Vs[32 * VPT];   //  9216 B
    __shared__ __align__(16) uint32_t Ps[128 * PPT];  // 18432 B

    const int bh = blockIdx.y;
    const int rb = blockIdx.x;   // 128-row block
    const int tid = threadIdx.x;
    const int lane = tid & 31;
    const int warp = tid >> 5;
    const int g = lane >> 2, t = lane & 3;

    // Q fragments for 2 row-blocks (rows warp*32+blk*16+{g,g+8}), once from gmem.
    const float* qbase = g_q + ((size_t)bh * SEQ + rb * 128) * DKH;
    uint32_t qa[2][8][4];
#pragma unroll
    for (int blk = 0; blk < 2; blk++) {
        const int r0 = warp * 32 + blk * 16 + g, r1 = r0 + 8;
#pragma unroll
        for (int ks = 0; ks < 8; ks++) {
            qa[blk][ks][0] = f2tf32(qbase[r0 * DKH + ks * 8 + t]);
            qa[blk][ks][1] = f2tf32(qbase[r1 * DKH + ks * 8 + t]);
            qa[blk][ks][2] = f2tf32(qbase[r0 * DKH + ks * 8 + t + 4]);
            qa[blk][ks][3] = f2tf32(qbase[r1 * DKH + ks * 8 + t + 4]);
        }
    }

    float m_[2][2], l_[2][2];
#pragma unroll
    for (int blk = 0; blk < 2; blk++) {
        m_[blk][0] = -INFINITY; m_[blk][1] = -INFINITY;
        l_[blk][0] = 0.0f;      l_[blk][1] = 0.0f;
    }
    float o[2][8][4];
#pragma unroll
    for (int blk = 0; blk < 2; blk++)
#pragma unroll
        for (int nt = 0; nt < 8; nt++)
#pragma unroll
            for (int j = 0; j < 4; j++) o[blk][nt][j] = 0.0f;

    const float scale = 0.125f;
    const int rowA[2] = {rb * 128 + warp * 32 + g, rb * 128 + warp * 32 + 16 + g};
    const int tmax = 4 * rb + 3;   // 32-col tiles covering <= rb*128+127

    const float* kbase = g_k + (size_t)bh * SEQ * DKH;
    const float* vbase = g_v + (size_t)bh * SEQ * DKH;

    for (int tt = 0; tt <= tmax; tt++) {
        __syncthreads();  // prior tile's K/V reads done
        const float* kb = kbase + (size_t)tt * 32 * DKH;
        const float* vb = vbase + (size_t)tt * 32 * DKH;
#pragma unroll
        for (int i = 0; i < 4; i++) {
            int e = tid + i * 128;
            int r = e >> 4, d4 = (e & 15) * 4;
            float4 kv = *(const float4*)(kb + r * DKH + d4);
            float4 vv = *(const float4*)(vb + r * DKH + d4);
            uint4 u;
            u.x = f2tf32(kv.x); u.y = f2tf32(kv.y); u.z = f2tf32(kv.z); u.w = f2tf32(kv.w);
            *(uint4*)&Ks[r * QPT + d4] = u;
            u.x = f2tf32(vv.x); u.y = f2tf32(vv.y); u.z = f2tf32(vv.z); u.w = f2tf32(vv.w);
            *(uint4*)&Vs[r * VPT + d4] = u;
        }
        __syncthreads();

        // S = Q K^T for both row-blocks; K b-frags loaded ONCE, used twice.
        float s_[2][4][4];
#pragma unroll
        for (int blk = 0; blk < 2; blk++)
#pragma unroll
            for (int nt = 0; nt < 4; nt++)
#pragma unroll
                for (int j = 0; j < 4; j++) s_[blk][nt][j] = 0.0f;

#pragma unroll
        for (int ks = 0; ks < 8; ks++) {
#pragma unroll
            for (int nt = 0; nt < 4; nt++) {
                uint32_t b[2];
                const uint32_t* kr = &Ks[(nt * 8 + g) * QPT + ks * 8];
                b[0] = kr[t];
                b[1] = kr[t + 4];
                mma_tf32(s_[0][nt], qa[0][ks], b);
                mma_tf32(s_[1][nt], qa[1][ks], b);
            }
        }

        // Online softmax (fp32), per row-block
        const bool masked = (tt >= 4 * rb);
        const int cbase = tt * 32 + 2 * t;
#pragma unroll
        for (int blk = 0; blk < 2; blk++) {
            float mx0 = -INFINITY, mx1 = -INFINITY;
#pragma unroll
            for (int nt = 0; nt < 4; nt++) {
#pragma unroll
                for (int j = 0; j < 4; j++) {
                    float v = s_[blk][nt][j] * scale;
                    const int col = cbase + nt * 8 + (j & 1);
                    const int row = rowA[blk] + (j >> 1) * 8;
                    if (masked && col > row) v = -INFINITY;
                    s_[blk][nt][j] = v;
                    if (j < 2) mx0 = fmaxf(mx0, v);
                    else mx1 = fmaxf(mx1, v);
                }
            }
            mx0 = fmaxf(mx0, __shfl_xor_sync(0xFFFFFFFFu, mx0, 1));
            mx0 = fmaxf(mx0, __shfl_xor_sync(0xFFFFFFFFu, mx0, 2));
            mx1 = fmaxf(mx1, __shfl_xor_sync(0xFFFFFFFFu, mx1, 1));
            mx1 = fmaxf(mx1, __shfl_xor_sync(0xFFFFFFFFu, mx1, 2));

            const float mn0 = fmaxf(m_[blk][0], mx0);
            const float mn1 = fmaxf(m_[blk][1], mx1);
            const float scl0 = __expf(m_[blk][0] - mn0);
            const float scl1 = __expf(m_[blk][1] - mn1);

            float rs0 = 0.0f, rs1 = 0.0f;
#pragma unroll
            for (int nt = 0; nt < 4; nt++) {
                float p0 = __expf(s_[blk][nt][0] - mn0);
                float p1 = __expf(s_[blk][nt][1] - mn0);
                float p2 = __expf(s_[blk][nt][2] - mn1);
                float p3 = __expf(s_[blk][nt][3] - mn1);
                rs0 += p0 + p1;
                rs1 += p2 + p3;
                uint32_t* pr = &Ps[(warp * 32 + blk * 16 + g) * PPT + nt * 8 + 2 * t];
                *(uint2*)pr = make_uint2(f2tf32(p0), f2tf32(p1));
                *(uint2*)(pr + 8 * PPT) = make_uint2(f2tf32(p2), f2tf32(p3));
            }
            rs0 += __shfl_xor_sync(0xFFFFFFFFu, rs0, 1);
            rs0 += __shfl_xor_sync(0xFFFFFFFFu, rs0, 2);
            rs1 += __shfl_xor_sync(0xFFFFFFFFu, rs1, 1);
            rs1 += __shfl_xor_sync(0xFFFFFFFFu, rs1, 2);

            l_[blk][0] = l_[blk][0] * scl0 + rs0;
            l_[blk][1] = l_[blk][1] * scl1 + rs1;
            m_[blk][0] = mn0;
            m_[blk][1] = mn1;

#pragma unroll
            for (int nt = 0; nt < 8; nt++) {
                o[blk][nt][0] *= scl0;
                o[blk][nt][1] *= scl0;
                o[blk][nt][2] *= scl1;
                o[blk][nt][3] *= scl1;
            }
        }
        __syncwarp();  // P visible within warp

        // O += P V : V b-frags loaded ONCE per (ks,nt), used for both blocks.
#pragma unroll
        for (int ks = 0; ks < 4; ks++) {
            uint32_t a0[4], a1[4];
            const uint32_t* pr0 = &Ps[(warp * 32 + g) * PPT + ks * 8];
            const uint32_t* pr1 = &Ps[(warp * 32 + 16 + g) * PPT + ks * 8];
            a0[0] = pr0[t];
            a0[1] = pr0[8 * PPT + t];
            a0[2] = pr0[t + 4];
            a0[3] = pr0[8 * PPT + t + 4];
            a1[0] = pr1[t];
            a1[1] = pr1[8 * PPT + t];
            a1[2] = pr1[t + 4];
            a1[3] = pr1[8 * PPT + t + 4];
#pragma unroll
            for (int nt = 0; nt < 8; nt++) {
                uint32_t b[2];
                b[0] = Vs[(ks * 8 + t) * VPT + nt * 8 + g];
                b[1] = Vs[(ks * 8 + t + 4) * VPT + nt * 8 + g];
                mma_tf32(o[0][nt], a0, b);
                mma_tf32(o[1][nt], a1, b);
            }
        }
        __syncwarp();  // P reads done before next tile overwrites
    }

    // Write merged-head layout: (b, l, h*64+dk)
    const int bb = bh >> 4, hh = bh & 15;
#pragma unroll
    for (int blk = 0; blk < 2; blk++) {
        const float inv0 = 1.0f / l_[blk][0];
        const float inv1 = 1.0f / l_[blk][1];
        float* base0 = g_attn + ((size_t)(bb * SEQ + rowA[blk])) * DMODEL + hh * 64;
        float* base1 = base0 + (size_t)8 * DMODEL;
#pragma unroll
        for (int nt = 0; nt < 8; nt++) {
            const int c = nt * 8 + 2 * t;
            *(float2*)(base0 + c) = make_float2(o[blk][nt][0] * inv0, o[blk][nt][1] * inv0);
            *(float2*)(base1 + c) = make_float2(o[blk][nt][2] * inv1, o[blk][nt][3] * inv1);
        }
    }
}

// ============================================================
// Launch: kernel launches ONLY
// ============================================================
extern "C" void kernel_launch(void* const* d_in, const int* in_sizes, int n_in,
                              void* d_out, int out_size) {
    const float* x = (const float*)d_in[0];
    const float* wq = (const float*)d_in[1];
    const float* wk = (const float*)d_in[2];
    const float* wv = (const float*)d_in[3];
    const float* wo = (const float*)d_in[4];
    float* out = (float*)d_out;

    dim3 qk_grid(DMODEL / 128, MTOT / 128, 2);  // (8, 32, 2): Q and K fused
    qk3_gemm<<<qk_grid, 256>>>(x, wq, wk);

    dim3 gemm_grid(DMODEL / 128, MTOT / 128);  // (8, 32)
    tf32_gemm<2><<<gemm_grid, 256>>>(x, wv, nullptr);  // V (tf32 TC)

    dim3 attn_grid(SEQ / 128, BHTOT);  // (16, 32)
    flash_attn_tc<<<attn_grid, 128>>>();

    tf32_gemm<3><<<gemm_grid, 256>>>(nullptr, wo, out);  // O (tf32 TC)
}

// round 13
// speedup vs baseline: 1.5238x; 1.5238x over previous
#include <cuda_runtime.h>
#include <cuda_bf16.h>
#include <math.h>
#include <stdint.h>

#define NHEADS 16
#define DKH 64
#define BATCH 2
#define SEQ 2048
#define DMODEL 1024
#define MTOT (BATCH * SEQ)      // 4096
#define BHTOT (BATCH * NHEADS)  // 32

// Scratch (__device__ globals: allocation-free)
__device__ float g_q[BHTOT * SEQ * DKH];
__device__ float g_k[BHTOT * SEQ * DKH];
__device__ float g_v[BHTOT * SEQ * DKH];
__device__ float g_attn[MTOT * DMODEL];

// ============================================================
// mma helpers (layouts HW-verified R4/R6/R9)
// ============================================================
__device__ __forceinline__ uint32_t f2tf32(float x) {
    uint32_t r;
    asm("cvt.rna.tf32.f32 %0, %1;" : "=r"(r) : "f"(x));
    return r;
}

__device__ __forceinline__ void mma_tf32(float d[4], const uint32_t a[4],
                                         const uint32_t b[2]) {
    asm volatile(
        "mma.sync.aligned.m16n8k8.row.col.f32.tf32.tf32.f32 "
        "{%0,%1,%2,%3}, {%4,%5,%6,%7}, {%8,%9}, {%0,%1,%2,%3};\n"
        : "+f"(d[0]), "+f"(d[1]), "+f"(d[2]), "+f"(d[3])
        : "r"(a[0]), "r"(a[1]), "r"(a[2]), "r"(a[3]), "r"(b[0]), "r"(b[1]));
}

__device__ __forceinline__ void mma_bf16(float d[4], const uint32_t a[4],
                                         const uint32_t b[2]) {
    asm volatile(
        "mma.sync.aligned.m16n8k16.row.col.f32.bf16.bf16.f32 "
        "{%0,%1,%2,%3}, {%4,%5,%6,%7}, {%8,%9}, {%0,%1,%2,%3};\n"
        : "+f"(d[0]), "+f"(d[1]), "+f"(d[2]), "+f"(d[3])
        : "r"(a[0]), "r"(a[1]), "r"(a[2]), "r"(a[3]), "r"(b[0]), "r"(b[1]));
}

__device__ __forceinline__ void cvt_hilo(float4 v, uint2& h, uint2& l) {
    __nv_bfloat16 h0 = __float2bfloat16_rn(v.x);
    __nv_bfloat16 h1 = __float2bfloat16_rn(v.y);
    __nv_bfloat16 h2 = __float2bfloat16_rn(v.z);
    __nv_bfloat16 h3 = __float2bfloat16_rn(v.w);
    __nv_bfloat16 l0 = __float2bfloat16_rn(v.x - __bfloat162float(h0));
    __nv_bfloat16 l1 = __float2bfloat16_rn(v.y - __bfloat162float(h1));
    __nv_bfloat16 l2 = __float2bfloat16_rn(v.z - __bfloat162float(h2));
    __nv_bfloat16 l3 = __float2bfloat16_rn(v.w - __bfloat162float(h3));
    __nv_bfloat162 hp0 = __halves2bfloat162(h0, h1);
    __nv_bfloat162 hp1 = __halves2bfloat162(h2, h3);
    __nv_bfloat162 lp0 = __halves2bfloat162(l0, l1);
    __nv_bfloat162 lp1 = __halves2bfloat162(l2, l3);
    h.x = *(uint32_t*)&hp0;
    h.y = *(uint32_t*)&hp1;
    l.x = *(uint32_t*)&lp0;
    l.y = *(uint32_t*)&lp1;
}

// ============================================================
// BF16x3 tensor-core GEMM for Q AND K projections, fused:
// grid.z = 0 -> (wq, g_q), 1 -> (wk, g_k). Split-heads epilogue.
// ============================================================
#define BP 12

__global__ __launch_bounds__(256, 2) void qk3_gemm(const float* __restrict__ Ain,
                                                   const float* __restrict__ Wq,
                                                   const float* __restrict__ Wk) {
    __shared__ __align__(16) uint32_t Ah[128 * BP];
    __shared__ __align__(16) uint32_t Al[128 * BP];
    __shared__ __align__(16) uint32_t Bh[128 * BP];
    __shared__ __align__(16) uint32_t Bl[128 * BP];

    const float* Bw = (blockIdx.z == 0) ? Wq : Wk;
    const int K = 1024;
    const int tid = threadIdx.x;
    const int lane = tid & 31, warp = tid >> 5;
    const int wm = warp >> 2, wn = warp & 3;
    const int g = lane >> 2, t = lane & 3;
    const int bm = blockIdx.y, bn = blockIdx.x;

    const int lm = tid >> 2;
    const int kw = (tid & 3) * 2;
    const int k4 = (tid & 3) * 4;

    const float* Ap = Ain + (size_t)(bm * 128 + lm) * K + k4;
    const float* Bp = Bw + (size_t)(bn * 128 + lm) * K + k4;

    float d[4][4][4];
#pragma unroll
    for (int i = 0; i < 4; i++)
#pragma unroll
        for (int j = 0; j < 4; j++)
#pragma unroll
            for (int c = 0; c < 4; c++) d[i][j][c] = 0.0f;

    float4 a0v = *(const float4*)(Ap);
    float4 a1v = *(const float4*)(Ap + 64 * K);
    float4 b0v = *(const float4*)(Bp);
    float4 b1v = *(const float4*)(Bp + 64 * K);

    for (int k0 = 0; k0 < K; k0 += 16) {
        uint2 h, l;
        cvt_hilo(a0v, h, l);
        *(uint2*)&Ah[lm * BP + kw] = h;
        *(uint2*)&Al[lm * BP + kw] = l;
        cvt_hilo(a1v, h, l);
        *(uint2*)&Ah[(lm + 64) * BP + kw] = h;
        *(uint2*)&Al[(lm + 64) * BP + kw] = l;
        cvt_hilo(b0v, h, l);
        *(uint2*)&Bh[lm * BP + kw] = h;
        *(uint2*)&Bl[lm * BP + kw] = l;
        cvt_hilo(b1v, h, l);
        *(uint2*)&Bh[(lm + 64) * BP + kw] = h;
        *(uint2*)&Bl[(lm + 64) * BP + kw] = l;
        __syncthreads();

        if (k0 + 16 < K) {
            a0v = *(const float4*)(Ap + k0 + 16);
            a1v = *(const float4*)(Ap + 64 * K + k0 + 16);
            b0v = *(const float4*)(Bp + k0 + 16);
            b1v = *(const float4*)(Bp + 64 * K + k0 + 16);
        }

        uint32_t afh[4][4], bfh[4][2];
#pragma unroll
        for (int mt = 0; mt < 4; mt++) {
            const int mb = wm * 64 + mt * 16 + g;
            afh[mt][0] = Ah[mb * BP + t];
            afh[mt][1] = Ah[(mb + 8) * BP + t];
            afh[mt][2] = Ah[mb * BP + t + 4];
            afh[mt][3] = Ah[(mb + 8) * BP + t + 4];
        }
#pragma unroll
        for (int nt = 0; nt < 4; nt++) {
            const int nb = wn * 32 + nt * 8 + g;
            bfh[nt][0] = Bh[nb * BP + t];
            bfh[nt][1] = Bh[nb * BP + t + 4];
        }
#pragma unroll
        for (int mt = 0; mt < 4; mt++)
#pragma unroll
            for (int nt = 0; nt < 4; nt++) mma_bf16(d[mt][nt], afh[mt], bfh[nt]);
        {
            uint32_t afl[4][4];
#pragma unroll
            for (int mt = 0; mt < 4; mt++) {
                const int mb = wm * 64 + mt * 16 + g;
                afl[mt][0] = Al[mb * BP + t];
                afl[mt][1] = Al[(mb + 8) * BP + t];
                afl[mt][2] = Al[mb * BP + t + 4];
                afl[mt][3] = Al[(mb + 8) * BP + t + 4];
            }
#pragma unroll
            for (int mt = 0; mt < 4; mt++)
#pragma unroll
                for (int nt = 0; nt < 4; nt++) mma_bf16(d[mt][nt], afl[mt], bfh[nt]);
        }
        {
            uint32_t bfl[4][2];
#pragma unroll
            for (int nt = 0; nt < 4; nt++) {
                const int nb = wn * 32 + nt * 8 + g;
                bfl[nt][0] = Bl[nb * BP + t];
                bfl[nt][1] = Bl[nb * BP + t + 4];
            }
#pragma unroll
            for (int mt = 0; mt < 4; mt++)
#pragma unroll
                for (int nt = 0; nt < 4; nt++) mma_bf16(d[mt][nt], afh[mt], bfl[nt]);
        }
        __syncthreads();
    }

    float* C = (blockIdx.z == 0) ? g_q : g_k;
#pragma unroll
    for (int mt = 0; mt < 4; mt++) {
#pragma unroll
        for (int nt = 0; nt < 4; nt++) {
            const int m0 = bm * 128 + wm * 64 + mt * 16 + g;
            const int n0 = bn * 128 + wn * 32 + nt * 8 + 2 * t;
#pragma unroll
            for (int half = 0; half < 2; half++) {
                const int m = m0 + half * 8;
                const int bb = m >> 11, ll = m & 2047;
                const int hh = n0 >> 6, dk = n0 & 63;
                float2* p = (float2*)&C[(((size_t)(bb * 16 + hh) * 2048) + ll) * 64 + dk];
                *p = make_float2(d[mt][nt][half * 2 + 0], d[mt][nt][half * 2 + 1]);
            }
        }
    }
}

// ============================================================
// Plain TF32 tensor-core GEMM (V-proj / O-proj). Unchanged.
// ============================================================
#define TP 20

template <int DEST>
__global__ __launch_bounds__(256, 2) void tf32_gemm(const float* __restrict__ Ain,
                                                    const float* __restrict__ Bw,
                                                    float* __restrict__ Cout) {
    __shared__ __align__(16) uint32_t As[128 * TP];
    __shared__ __align__(16) uint32_t Bs[128 * TP];

    const float* A = (DEST == 3) ? (const float*)g_attn : Ain;
    const int K = 1024;
    const int tid = threadIdx.x;
    const int lane = tid & 31, warp = tid >> 5;
    const int wm = warp >> 2, wn = warp & 3;
    const int g = lane >> 2, t = lane & 3;
    const int bm = blockIdx.y, bn = blockIdx.x;

    const int lm = tid >> 2;
    const int k4 = (tid & 3) * 4;

    const float* Ap = A + (size_t)(bm * 128 + lm) * K + k4;
    const float* Bp = Bw + (size_t)(bn * 128 + lm) * K + k4;

    float d[4][4][4];
#pragma unroll
    for (int i = 0; i < 4; i++)
#pragma unroll
        for (int j = 0; j < 4; j++)
#pragma unroll
            for (int c = 0; c < 4; c++) d[i][j][c] = 0.0f;

    float4 a0v = *(const float4*)(Ap);
    float4 a1v = *(const float4*)(Ap + 64 * K);
    float4 b0v = *(const float4*)(Bp);
    float4 b1v = *(const float4*)(Bp + 64 * K);

    for (int k0 = 0; k0 < K; k0 += 16) {
        uint4 s;
        s.x = f2tf32(a0v.x); s.y = f2tf32(a0v.y); s.z = f2tf32(a0v.z); s.w = f2tf32(a0v.w);
        *(uint4*)&As[lm * TP + k4] = s;
        s.x = f2tf32(a1v.x); s.y = f2tf32(a1v.y); s.z = f2tf32(a1v.z); s.w = f2tf32(a1v.w);
        *(uint4*)&As[(lm + 64) * TP + k4] = s;
        s.x = f2tf32(b0v.x); s.y = f2tf32(b0v.y); s.z = f2tf32(b0v.z); s.w = f2tf32(b0v.w);
        *(uint4*)&Bs[lm * TP + k4] = s;
        s.x = f2tf32(b1v.x); s.y = f2tf32(b1v.y); s.z = f2tf32(b1v.z); s.w = f2tf32(b1v.w);
        *(uint4*)&Bs[(lm + 64) * TP + k4] = s;
        __syncthreads();

        if (k0 + 16 < K) {
            a0v = *(const float4*)(Ap + k0 + 16);
            a1v = *(const float4*)(Ap + 64 * K + k0 + 16);
            b0v = *(const float4*)(Bp + k0 + 16);
            b1v = *(const float4*)(Bp + 64 * K + k0 + 16);
        }

#pragma unroll
        for (int ks = 0; ks < 16; ks += 8) {
            uint32_t af[4][4], bf[4][2];
#pragma unroll
            for (int mt = 0; mt < 4; mt++) {
                const int mb = wm * 64 + mt * 16 + g;
                af[mt][0] = As[mb * TP + ks + t];
                af[mt][1] = As[(mb + 8) * TP + ks + t];
                af[mt][2] = As[mb * TP + ks + t + 4];
                af[mt][3] = As[(mb + 8) * TP + ks + t + 4];
            }
#pragma unroll
            for (int nt = 0; nt < 4; nt++) {
                const int nb = wn * 32 + nt * 8 + g;
                bf[nt][0] = Bs[nb * TP + ks + t];
                bf[nt][1] = Bs[nb * TP + ks + t + 4];
            }
#pragma unroll
            for (int mt = 0; mt < 4; mt++)
#pragma unroll
                for (int nt = 0; nt < 4; nt++) mma_tf32(d[mt][nt], af[mt], bf[nt]);
        }
        __syncthreads();
    }

#pragma unroll
    for (int mt = 0; mt < 4; mt++) {
#pragma unroll
        for (int nt = 0; nt < 4; nt++) {
            const int m0 = bm * 128 + wm * 64 + mt * 16 + g;
            const int n0 = bn * 128 + wn * 32 + nt * 8 + 2 * t;
#pragma unroll
            for (int half = 0; half < 2; half++) {
                const int m = m0 + half * 8;
                const float v0 = d[mt][nt][half * 2 + 0];
                const float v1 = d[mt][nt][half * 2 + 1];
                if (DEST == 3) {
                    float2* p = (float2*)&Cout[(size_t)m * 1024 + n0];
                    *p = make_float2(v0, v1);
                } else {
                    const int bb = m >> 11, ll = m & 2047;
                    const int hh = n0 >> 6, dk = n0 & 63;
                    float2* p = (float2*)&g_v[(((size_t)(bb * 16 + hh) * 2048) + ll) * 64 + dk];
                    *p = make_float2(v0, v1);
                }
            }
        }
    }
}

// ============================================================
// Tensor-core causal flash attention (tf32 mma, fp32 softmax).
// R13: per-warp program IDENTICAL to R11 (16 Q rows/warp, qa in
// regs, 32-col K/V tiles) but 8 warps/CTA cover 128 Q rows against
// one shared K/V tile: fill traffic + syncs per unit work halve,
// register footprint unchanged (no R12 spills).
// Smem 36.3KB static.
// ============================================================
#define QPT 68
#define VPT 72
#define PPT 36

__global__ __launch_bounds__(256) void flash_attn_tc() {
    __shared__ __align__(16) uint32_t Ks[32 * QPT];   //  8704 B
    __shared__ __align__(16) uint32_t Vs[32 * VPT];   //  9216 B
    __shared__ __align__(16) uint32_t Ps[128 * PPT];  // 18432 B

    const int bh = blockIdx.y;
    const int rb = blockIdx.x;   // 128-row Q block
    const int tid = threadIdx.x;
    const int lane = tid & 31;
    const int warp = tid >> 5;   // 0..7, warp owns rows warp*16..+15
    const int g = lane >> 2, t = lane & 3;

    // Q fragments: loaded once from gmem (read-once data).
    const float* qbase = g_q + ((size_t)bh * SEQ + rb * 128) * DKH;
    const int r0 = warp * 16 + g, r1 = r0 + 8;
    uint32_t qa[8][4];
#pragma unroll
    for (int ks = 0; ks < 8; ks++) {
        qa[ks][0] = f2tf32(qbase[r0 * DKH + ks * 8 + t]);
        qa[ks][1] = f2tf32(qbase[r1 * DKH + ks * 8 + t]);
        qa[ks][2] = f2tf32(qbase[r0 * DKH + ks * 8 + t + 4]);
        qa[ks][3] = f2tf32(qbase[r1 * DKH + ks * 8 + t + 4]);
    }

    float m0 = -INFINITY, m1 = -INFINITY, l0 = 0.0f, l1 = 0.0f;
    float o[8][4];
#pragma unroll
    for (int nt = 0; nt < 8; nt++)
#pragma unroll
        for (int j = 0; j < 4; j++) o[nt][j] = 0.0f;

    const float scale = 0.125f;
    const int row0 = rb * 128 + warp * 16 + g;
    const int tmax = 4 * rb + 3;   // 32-col tiles covering <= rb*128+127

    const float* kbase = g_k + (size_t)bh * SEQ * DKH;
    const float* vbase = g_v + (size_t)bh * SEQ * DKH;

    for (int tt = 0; tt <= tmax; tt++) {
        __syncthreads();  // prior tile's K/V reads done
        // K,V tile fill: 512 float4 slots each / 256 threads = 2 per thread.
        const float* kb = kbase + (size_t)tt * 32 * DKH;
        const float* vb = vbase + (size_t)tt * 32 * DKH;
#pragma unroll
        for (int i = 0; i < 2; i++) {
            int e = tid + i * 256;
            int r = e >> 4, d4 = (e & 15) * 4;
            float4 kv = *(const float4*)(kb + r * DKH + d4);
            float4 vv = *(const float4*)(vb + r * DKH + d4);
            uint4 u;
            u.x = f2tf32(kv.x); u.y = f2tf32(kv.y); u.z = f2tf32(kv.z); u.w = f2tf32(kv.w);
            *(uint4*)&Ks[r * QPT + d4] = u;
            u.x = f2tf32(vv.x); u.y = f2tf32(vv.y); u.z = f2tf32(vv.z); u.w = f2tf32(vv.w);
            *(uint4*)&Vs[r * VPT + d4] = u;
        }
        __syncthreads();

        // S = Q K^T
        float s_[4][4];
#pragma unroll
        for (int nt = 0; nt < 4; nt++)
#pragma unroll
            for (int j = 0; j < 4; j++) s_[nt][j] = 0.0f;

#pragma unroll
        for (int ks = 0; ks < 8; ks++) {
#pragma unroll
            for (int nt = 0; nt < 4; nt++) {
                uint32_t b[2];
                const uint32_t* kr = &Ks[(nt * 8 + g) * QPT + ks * 8];
                b[0] = kr[t];
                b[1] = kr[t + 4];
                mma_tf32(s_[nt], qa[ks], b);
            }
        }

        // Online softmax (fp32)
        const bool masked = (tt >= 4 * rb);
        const int cbase = tt * 32 + 2 * t;
        float mx0 = -INFINITY, mx1 = -INFINITY;
#pragma unroll
        for (int nt = 0; nt < 4; nt++) {
#pragma unroll
            for (int j = 0; j < 4; j++) {
                float v = s_[nt][j] * scale;
                const int col = cbase + nt * 8 + (j & 1);
                const int row = row0 + (j >> 1) * 8;
                if (masked && col > row) v = -INFINITY;
                s_[nt][j] = v;
                if (j < 2) mx0 = fmaxf(mx0, v);
                else mx1 = fmaxf(mx1, v);
            }
        }
        mx0 = fmaxf(mx0, __shfl_xor_sync(0xFFFFFFFFu, mx0, 1));
        mx0 = fmaxf(mx0, __shfl_xor_sync(0xFFFFFFFFu, mx0, 2));
        mx1 = fmaxf(mx1, __shfl_xor_sync(0xFFFFFFFFu, mx1, 1));
        mx1 = fmaxf(mx1, __shfl_xor_sync(0xFFFFFFFFu, mx1, 2));

        const float mn0 = fmaxf(m0, mx0);
        const float mn1 = fmaxf(m1, mx1);
        const float scl0 = __expf(m0 - mn0);
        const float scl1 = __expf(m1 - mn1);

        float rs0 = 0.0f, rs1 = 0.0f;
#pragma unroll
        for (int nt = 0; nt < 4; nt++) {
            float p0 = __expf(s_[nt][0] - mn0);
            float p1 = __expf(s_[nt][1] - mn0);
            float p2 = __expf(s_[nt][2] - mn1);
            float p3 = __expf(s_[nt][3] - mn1);
            rs0 += p0 + p1;
            rs1 += p2 + p3;
            uint32_t* pr = &Ps[(warp * 16 + g) * PPT + nt * 8 + 2 * t];
            *(uint2*)pr = make_uint2(f2tf32(p0), f2tf32(p1));
            *(uint2*)(pr + 8 * PPT) = make_uint2(f2tf32(p2), f2tf32(p3));
        }
        rs0 += __shfl_xor_sync(0xFFFFFFFFu, rs0, 1);
        rs0 += __shfl_xor_sync(0xFFFFFFFFu, rs0, 2);
        rs1 += __shfl_xor_sync(0xFFFFFFFFu, rs1, 1);
        rs1 += __shfl_xor_sync(0xFFFFFFFFu, rs1, 2);

        l0 = l0 * scl0 + rs0;
        l1 = l1 * scl1 + rs1;
        m0 = mn0;
        m1 = mn1;

#pragma unroll
        for (int nt = 0; nt < 8; nt++) {
            o[nt][0] *= scl0;
            o[nt][1] *= scl0;
            o[nt][2] *= scl1;
            o[nt][3] *= scl1;
        }
        __syncwarp();

        // O += P V
#pragma unroll
        for (int ks = 0; ks < 4; ks++) {
            uint32_t a[4];
            const uint32_t* pr = &Ps[(warp * 16 + g) * PPT + ks * 8];
            a[0] = pr[t];
            a[1] = pr[8 * PPT + t];
            a[2] = pr[t + 4];
            a[3] = pr[8 * PPT + t + 4];
#pragma unroll
            for (int nt = 0; nt < 8; nt++) {
                uint32_t b[2];
                b[0] = Vs[(ks * 8 + t) * VPT + nt * 8 + g];
                b[1] = Vs[(ks * 8 + t + 4) * VPT + nt * 8 + g];
                mma_tf32(o[nt], a, b);
            }
        }
        __syncwarp();  // P reads done before next tile overwrites
    }

    // Write merged-head layout: (b, l, h*64+dk)
    const int bb = bh >> 4, hh = bh & 15;
    const float inv0 = 1.0f / l0;
    const float inv1 = 1.0f / l1;
    float* base0 = g_attn + ((size_t)(bb * SEQ + row0)) * DMODEL + hh * 64;
    float* base1 = base0 + (size_t)8 * DMODEL;
#pragma unroll
    for (int nt = 0; nt < 8; nt++) {
        const int c = nt * 8 + 2 * t;
        *(float2*)(base0 + c) = make_float2(o[nt][0] * inv0, o[nt][1] * inv0);
        *(float2*)(base1 + c) = make_float2(o[nt][2] * inv1, o[nt][3] * inv1);
    }
}

// ============================================================
// Launch: kernel launches ONLY
// ============================================================
extern "C" void kernel_launch(void* const* d_in, const int* in_sizes, int n_in,
                              void* d_out, int out_size) {
    const float* x = (const float*)d_in[0];
    const float* wq = (const float*)d_in[1];
    const float* wk = (const float*)d_in[2];
    const float* wv = (const float*)d_in[3];
    const float* wo = (const float*)d_in[4];
    float* out = (float*)d_out;

    dim3 qk_grid(DMODEL / 128, MTOT / 128, 2);  // (8, 32, 2): Q and K fused
    qk3_gemm<<<qk_grid, 256>>>(x, wq, wk);

    dim3 gemm_grid(DMODEL / 128, MTOT / 128);  // (8, 32)
    tf32_gemm<2><<<gemm_grid, 256>>>(x, wv, nullptr);  // V (tf32 TC)

    dim3 attn_grid(SEQ / 128, BHTOT);  // (16, 32)
    flash_attn_tc<<<attn_grid, 256>>>();

    tf32_gemm<3><<<gemm_grid, 256>>>(nullptr, wo, out);  // O (tf32 TC)
}

// round 14
// speedup vs baseline: 1.5636x; 1.0261x over previous
#include <cuda_runtime.h>
#include <cuda_bf16.h>
#include <math.h>
#include <stdint.h>

#define NHEADS 16
#define DKH 64
#define BATCH 2
#define SEQ 2048
#define DMODEL 1024
#define MTOT (BATCH * SEQ)      // 4096
#define BHTOT (BATCH * NHEADS)  // 32

// Scratch (__device__ globals: allocation-free)
__device__ float g_q[BHTOT * SEQ * DKH];
__device__ float g_k[BHTOT * SEQ * DKH];
__device__ float g_v[BHTOT * SEQ * DKH];
__device__ float g_attn[MTOT * DMODEL];

// ============================================================
// mma helpers (layouts HW-verified R4/R6/R9)
// ============================================================
__device__ __forceinline__ uint32_t f2tf32(float x) {
    uint32_t r;
    asm("cvt.rna.tf32.f32 %0, %1;" : "=r"(r) : "f"(x));
    return r;
}

__device__ __forceinline__ void mma_tf32(float d[4], const uint32_t a[4],
                                         const uint32_t b[2]) {
    asm volatile(
        "mma.sync.aligned.m16n8k8.row.col.f32.tf32.tf32.f32 "
        "{%0,%1,%2,%3}, {%4,%5,%6,%7}, {%8,%9}, {%0,%1,%2,%3};\n"
        : "+f"(d[0]), "+f"(d[1]), "+f"(d[2]), "+f"(d[3])
        : "r"(a[0]), "r"(a[1]), "r"(a[2]), "r"(a[3]), "r"(b[0]), "r"(b[1]));
}

__device__ __forceinline__ void mma_bf16(float d[4], const uint32_t a[4],
                                         const uint32_t b[2]) {
    asm volatile(
        "mma.sync.aligned.m16n8k16.row.col.f32.bf16.bf16.f32 "
        "{%0,%1,%2,%3}, {%4,%5,%6,%7}, {%8,%9}, {%0,%1,%2,%3};\n"
        : "+f"(d[0]), "+f"(d[1]), "+f"(d[2]), "+f"(d[3])
        : "r"(a[0]), "r"(a[1]), "r"(a[2]), "r"(a[3]), "r"(b[0]), "r"(b[1]));
}

__device__ __forceinline__ void cvt_hilo(float4 v, uint2& h, uint2& l) {
    __nv_bfloat16 h0 = __float2bfloat16_rn(v.x);
    __nv_bfloat16 h1 = __float2bfloat16_rn(v.y);
    __nv_bfloat16 h2 = __float2bfloat16_rn(v.z);
    __nv_bfloat16 h3 = __float2bfloat16_rn(v.w);
    __nv_bfloat16 l0 = __float2bfloat16_rn(v.x - __bfloat162float(h0));
    __nv_bfloat16 l1 = __float2bfloat16_rn(v.y - __bfloat162float(h1));
    __nv_bfloat16 l2 = __float2bfloat16_rn(v.z - __bfloat162float(h2));
    __nv_bfloat16 l3 = __float2bfloat16_rn(v.w - __bfloat162float(h3));
    __nv_bfloat162 hp0 = __halves2bfloat162(h0, h1);
    __nv_bfloat162 hp1 = __halves2bfloat162(h2, h3);
    __nv_bfloat162 lp0 = __halves2bfloat162(l0, l1);
    __nv_bfloat162 lp1 = __halves2bfloat162(l2, l3);
    h.x = *(uint32_t*)&hp0;
    h.y = *(uint32_t*)&hp1;
    l.x = *(uint32_t*)&lp0;
    l.y = *(uint32_t*)&lp1;
}

// ============================================================
// BF16x3 tensor-core GEMM for Q AND K projections, fused
// (grid.z = 0 -> wq/g_q, 1 -> wk/g_k). R14: double-buffered smem,
// ONE __syncthreads per BK=16 iteration. Smem = 49152B exactly.
// ============================================================
#define BP 12

__global__ __launch_bounds__(256, 2) void qk3_gemm(const float* __restrict__ Ain,
                                                   const float* __restrict__ Wq,
                                                   const float* __restrict__ Wk) {
    __shared__ __align__(16) uint32_t Ah[2][128 * BP];
    __shared__ __align__(16) uint32_t Al[2][128 * BP];
    __shared__ __align__(16) uint32_t Bh[2][128 * BP];
    __shared__ __align__(16) uint32_t Bl[2][128 * BP];

    const float* Bw = (blockIdx.z == 0) ? Wq : Wk;
    const int K = 1024;
    const int tid = threadIdx.x;
    const int lane = tid & 31, warp = tid >> 5;
    const int wm = warp >> 2, wn = warp & 3;
    const int g = lane >> 2, t = lane & 3;
    const int bm = blockIdx.y, bn = blockIdx.x;

    const int lm = tid >> 2;
    const int kw = (tid & 3) * 2;
    const int k4 = (tid & 3) * 4;

    const float* Ap = Ain + (size_t)(bm * 128 + lm) * K + k4;
    const float* Bp = Bw + (size_t)(bn * 128 + lm) * K + k4;

    float d[4][4][4];
#pragma unroll
    for (int i = 0; i < 4; i++)
#pragma unroll
        for (int j = 0; j < 4; j++)
#pragma unroll
            for (int c = 0; c < 4; c++) d[i][j][c] = 0.0f;

    // Prologue: load + convert + store tile 0 into buffer 0.
    {
        float4 a0v = *(const float4*)(Ap);
        float4 a1v = *(const float4*)(Ap + 64 * K);
        float4 b0v = *(const float4*)(Bp);
        float4 b1v = *(const float4*)(Bp + 64 * K);
        uint2 h, l;
        cvt_hilo(a0v, h, l);
        *(uint2*)&Ah[0][lm * BP + kw] = h;
        *(uint2*)&Al[0][lm * BP + kw] = l;
        cvt_hilo(a1v, h, l);
        *(uint2*)&Ah[0][(lm + 64) * BP + kw] = h;
        *(uint2*)&Al[0][(lm + 64) * BP + kw] = l;
        cvt_hilo(b0v, h, l);
        *(uint2*)&Bh[0][lm * BP + kw] = h;
        *(uint2*)&Bl[0][lm * BP + kw] = l;
        cvt_hilo(b1v, h, l);
        *(uint2*)&Bh[0][(lm + 64) * BP + kw] = h;
        *(uint2*)&Bl[0][(lm + 64) * BP + kw] = l;
    }
    __syncthreads();

    for (int k0 = 0; k0 < K; k0 += 16) {
        const int cur = (k0 >> 4) & 1;
        const bool have_next = (k0 + 16 < K);

        // Prefetch next tile to registers (overlaps the mma phase).
        float4 a0v, a1v, b0v, b1v;
        if (have_next) {
            a0v = *(const float4*)(Ap + k0 + 16);
            a1v = *(const float4*)(Ap + 64 * K + k0 + 16);
            b0v = *(const float4*)(Bp + k0 + 16);
            b1v = *(const float4*)(Bp + 64 * K + k0 + 16);
        }

        // mma phase on buffer cur.
        uint32_t afh[4][4], bfh[4][2];
#pragma unroll
        for (int mt = 0; mt < 4; mt++) {
            const int mb = wm * 64 + mt * 16 + g;
            afh[mt][0] = Ah[cur][mb * BP + t];
            afh[mt][1] = Ah[cur][(mb + 8) * BP + t];
            afh[mt][2] = Ah[cur][mb * BP + t + 4];
            afh[mt][3] = Ah[cur][(mb + 8) * BP + t + 4];
        }
#pragma unroll
        for (int nt = 0; nt < 4; nt++) {
            const int nb = wn * 32 + nt * 8 + g;
            bfh[nt][0] = Bh[cur][nb * BP + t];
            bfh[nt][1] = Bh[cur][nb * BP + t + 4];
        }
#pragma unroll
        for (int mt = 0; mt < 4; mt++)
#pragma unroll
            for (int nt = 0; nt < 4; nt++) mma_bf16(d[mt][nt], afh[mt], bfh[nt]);
        {
            uint32_t afl[4][4];
#pragma unroll
            for (int mt = 0; mt < 4; mt++) {
                const int mb = wm * 64 + mt * 16 + g;
                afl[mt][0] = Al[cur][mb * BP + t];
                afl[mt][1] = Al[cur][(mb + 8) * BP + t];
                afl[mt][2] = Al[cur][mb * BP + t + 4];
                afl[mt][3] = Al[cur][(mb + 8) * BP + t + 4];
            }
#pragma unroll
            for (int mt = 0; mt < 4; mt++)
#pragma unroll
                for (int nt = 0; nt < 4; nt++) mma_bf16(d[mt][nt], afl[mt], bfh[nt]);
        }
        {
            uint32_t bfl[4][2];
#pragma unroll
            for (int nt = 0; nt < 4; nt++) {
                const int nb = wn * 32 + nt * 8 + g;
                bfl[nt][0] = Bl[cur][nb * BP + t];
                bfl[nt][1] = Bl[cur][nb * BP + t + 4];
            }
#pragma unroll
            for (int mt = 0; mt < 4; mt++)
#pragma unroll
                for (int nt = 0; nt < 4; nt++) mma_bf16(d[mt][nt], afh[mt], bfl[nt]);
        }

        // Store prefetched tile into buffer cur^1; ONE sync per iteration.
        if (have_next) {
            const int nxt = cur ^ 1;
            uint2 h, l;
            cvt_hilo(a0v, h, l);
            *(uint2*)&Ah[nxt][lm * BP + kw] = h;
            *(uint2*)&Al[nxt][lm * BP + kw] = l;
            cvt_hilo(a1v, h, l);
            *(uint2*)&Ah[nxt][(lm + 64) * BP + kw] = h;
            *(uint2*)&Al[nxt][(lm + 64) * BP + kw] = l;
            cvt_hilo(b0v, h, l);
            *(uint2*)&Bh[nxt][lm * BP + kw] = h;
            *(uint2*)&Bl[nxt][lm * BP + kw] = l;
            cvt_hilo(b1v, h, l);
            *(uint2*)&Bh[nxt][(lm + 64) * BP + kw] = h;
            *(uint2*)&Bl[nxt][(lm + 64) * BP + kw] = l;
        }
        __syncthreads();
    }

    float* C = (blockIdx.z == 0) ? g_q : g_k;
#pragma unroll
    for (int mt = 0; mt < 4; mt++) {
#pragma unroll
        for (int nt = 0; nt < 4; nt++) {
            const int m0 = bm * 128 + wm * 64 + mt * 16 + g;
            const int n0 = bn * 128 + wn * 32 + nt * 8 + 2 * t;
#pragma unroll
            for (int half = 0; half < 2; half++) {
                const int m = m0 + half * 8;
                const int bb = m >> 11, ll = m & 2047;
                const int hh = n0 >> 6, dk = n0 & 63;
                float2* p = (float2*)&C[(((size_t)(bb * 16 + hh) * 2048) + ll) * 64 + dk];
                *p = make_float2(d[mt][nt][half * 2 + 0], d[mt][nt][half * 2 + 1]);
            }
        }
    }
}

// ============================================================
// Plain TF32 tensor-core GEMM (V-proj / O-proj).
// R14: double-buffered smem, ONE sync per BK=16 iter. Smem 40KB.
// ============================================================
#define TP 20

template <int DEST>
__global__ __launch_bounds__(256, 2) void tf32_gemm(const float* __restrict__ Ain,
                                                    const float* __restrict__ Bw,
                                                    float* __restrict__ Cout) {
    __shared__ __align__(16) uint32_t As[2][128 * TP];
    __shared__ __align__(16) uint32_t Bs[2][128 * TP];

    const float* A = (DEST == 3) ? (const float*)g_attn : Ain;
    const int K = 1024;
    const int tid = threadIdx.x;
    const int lane = tid & 31, warp = tid >> 5;
    const int wm = warp >> 2, wn = warp & 3;
    const int g = lane >> 2, t = lane & 3;
    const int bm = blockIdx.y, bn = blockIdx.x;

    const int lm = tid >> 2;
    const int k4 = (tid & 3) * 4;

    const float* Ap = A + (size_t)(bm * 128 + lm) * K + k4;
    const float* Bp = Bw + (size_t)(bn * 128 + lm) * K + k4;

    float d[4][4][4];
#pragma unroll
    for (int i = 0; i < 4; i++)
#pragma unroll
        for (int j = 0; j < 4; j++)
#pragma unroll
            for (int c = 0; c < 4; c++) d[i][j][c] = 0.0f;

    // Prologue: tile 0 -> buffer 0.
    {
        float4 a0v = *(const float4*)(Ap);
        float4 a1v = *(const float4*)(Ap + 64 * K);
        float4 b0v = *(const float4*)(Bp);
        float4 b1v = *(const float4*)(Bp + 64 * K);
        uint4 s;
        s.x = f2tf32(a0v.x); s.y = f2tf32(a0v.y); s.z = f2tf32(a0v.z); s.w = f2tf32(a0v.w);
        *(uint4*)&As[0][lm * TP + k4] = s;
        s.x = f2tf32(a1v.x); s.y = f2tf32(a1v.y); s.z = f2tf32(a1v.z); s.w = f2tf32(a1v.w);
        *(uint4*)&As[0][(lm + 64) * TP + k4] = s;
        s.x = f2tf32(b0v.x); s.y = f2tf32(b0v.y); s.z = f2tf32(b0v.z); s.w = f2tf32(b0v.w);
        *(uint4*)&Bs[0][lm * TP + k4] = s;
        s.x = f2tf32(b1v.x); s.y = f2tf32(b1v.y); s.z = f2tf32(b1v.z); s.w = f2tf32(b1v.w);
        *(uint4*)&Bs[0][(lm + 64) * TP + k4] = s;
    }
    __syncthreads();

    for (int k0 = 0; k0 < K; k0 += 16) {
        const int cur = (k0 >> 4) & 1;
        const bool have_next = (k0 + 16 < K);

        float4 a0v, a1v, b0v, b1v;
        if (have_next) {
            a0v = *(const float4*)(Ap + k0 + 16);
            a1v = *(const float4*)(Ap + 64 * K + k0 + 16);
            b0v = *(const float4*)(Bp + k0 + 16);
            b1v = *(const float4*)(Bp + 64 * K + k0 + 16);
        }

#pragma unroll
        for (int ks = 0; ks < 16; ks += 8) {
            uint32_t af[4][4], bf[4][2];
#pragma unroll
            for (int mt = 0; mt < 4; mt++) {
                const int mb = wm * 64 + mt * 16 + g;
                af[mt][0] = As[cur][mb * TP + ks + t];
                af[mt][1] = As[cur][(mb + 8) * TP + ks + t];
                af[mt][2] = As[cur][mb * TP + ks + t + 4];
                af[mt][3] = As[cur][(mb + 8) * TP + ks + t + 4];
            }
#pragma unroll
            for (int nt = 0; nt < 4; nt++) {
                const int nb = wn * 32 + nt * 8 + g;
                bf[nt][0] = Bs[cur][nb * TP + ks + t];
                bf[nt][1] = Bs[cur][nb * TP + ks + t + 4];
            }
#pragma unroll
            for (int mt = 0; mt < 4; mt++)
#pragma unroll
                for (int nt = 0; nt < 4; nt++) mma_tf32(d[mt][nt], af[mt], bf[nt]);
        }

        if (have_next) {
            const int nxt = cur ^ 1;
            uint4 s;
            s.x = f2tf32(a0v.x); s.y = f2tf32(a0v.y); s.z = f2tf32(a0v.z); s.w = f2tf32(a0v.w);
            *(uint4*)&As[nxt][lm * TP + k4] = s;
            s.x = f2tf32(a1v.x); s.y = f2tf32(a1v.y); s.z = f2tf32(a1v.z); s.w = f2tf32(a1v.w);
            *(uint4*)&As[nxt][(lm + 64) * TP + k4] = s;
            s.x = f2tf32(b0v.x); s.y = f2tf32(b0v.y); s.z = f2tf32(b0v.z); s.w = f2tf32(b0v.w);
            *(uint4*)&Bs[nxt][lm * TP + k4] = s;
            s.x = f2tf32(b1v.x); s.y = f2tf32(b1v.y); s.z = f2tf32(b1v.z); s.w = f2tf32(b1v.w);
            *(uint4*)&Bs[nxt][(lm + 64) * TP + k4] = s;
        }
        __syncthreads();
    }

#pragma unroll
    for (int mt = 0; mt < 4; mt++) {
#pragma unroll
        for (int nt = 0; nt < 4; nt++) {
            const int m0 = bm * 128 + wm * 64 + mt * 16 + g;
            const int n0 = bn * 128 + wn * 32 + nt * 8 + 2 * t;
#pragma unroll
            for (int half = 0; half < 2; half++) {
                const int m = m0 + half * 8;
                const float v0 = d[mt][nt][half * 2 + 0];
                const float v1 = d[mt][nt][half * 2 + 1];
                if (DEST == 3) {
                    float2* p = (float2*)&Cout[(size_t)m * 1024 + n0];
                    *p = make_float2(v0, v1);
                } else {
                    const int bb = m >> 11, ll = m & 2047;
                    const int hh = n0 >> 6, dk = n0 & 63;
                    float2* p = (float2*)&g_v[(((size_t)(bb * 16 + hh) * 2048) + ll) * 64 + dk];
                    *p = make_float2(v0, v1);
                }
            }
        }
    }
}

// ============================================================
// Tensor-core causal flash attention — EXACT R8 config (proven
// 207us, 128 regs, 4 CTAs/SM): 128 threads, 4 warps, 16 Q rows/warp,
// Q frags from gmem once, single-buffered 32-col K/V tiles.
// ============================================================
#define QPT 68
#define VPT 72
#define PPT 36

__global__ __launch_bounds__(128, 4) void flash_attn_tc() {
    __shared__ __align__(16) uint32_t Ks[32 * QPT];  // 8704 B
    __shared__ __align__(16) uint32_t Vs[32 * VPT];  // 9216 B
    __shared__ __align__(16) uint32_t Ps[64 * PPT];  // 9216 B

    const int bh = blockIdx.y;
    const int rb = blockIdx.x;
    const int tid = threadIdx.x;
    const int lane = tid & 31;
    const int warp = tid >> 5;
    const int g = lane >> 2, t = lane & 3;

    const float* qbase = g_q + ((size_t)bh * SEQ + rb * 64) * DKH;
    const int r0 = warp * 16 + g, r1 = r0 + 8;
    uint32_t qa[8][4];
#pragma unroll
    for (int ks = 0; ks < 8; ks++) {
        qa[ks][0] = f2tf32(qbase[r0 * DKH + ks * 8 + t]);
        qa[ks][1] = f2tf32(qbase[r1 * DKH + ks * 8 + t]);
        qa[ks][2] = f2tf32(qbase[r0 * DKH + ks * 8 + t + 4]);
        qa[ks][3] = f2tf32(qbase[r1 * DKH + ks * 8 + t + 4]);
    }

    float m0 = -INFINITY, m1 = -INFINITY, l0 = 0.0f, l1 = 0.0f;
    float o[8][4];
#pragma unroll
    for (int nt = 0; nt < 8; nt++)
#pragma unroll
        for (int j = 0; j < 4; j++) o[nt][j] = 0.0f;

    const float scale = 0.125f;
    const int row0 = rb * 64 + warp * 16 + g;
    const int tmax = 2 * rb + 1;

    for (int tt = 0; tt <= tmax; tt++) {
        __syncthreads();
        const float* kb = g_k + ((size_t)bh * SEQ + tt * 32) * DKH;
        const float* vb = g_v + ((size_t)bh * SEQ + tt * 32) * DKH;
#pragma unroll
        for (int i = 0; i < 4; i++) {
            int e = tid + i * 128;
            int r = e >> 4, d4 = (e & 15) * 4;
            float4 kv = *(const float4*)(kb + r * DKH + d4);
            float4 vv = *(const float4*)(vb + r * DKH + d4);
            uint4 u;
            u.x = f2tf32(kv.x); u.y = f2tf32(kv.y); u.z = f2tf32(kv.z); u.w = f2tf32(kv.w);
            *(uint4*)&Ks[r * QPT + d4] = u;
            u.x = f2tf32(vv.x); u.y = f2tf32(vv.y); u.z = f2tf32(vv.z); u.w = f2tf32(vv.w);
            *(uint4*)&Vs[r * VPT + d4] = u;
        }
        __syncthreads();

        float s_[4][4];
#pragma unroll
        for (int nt = 0; nt < 4; nt++)
#pragma unroll
            for (int j = 0; j < 4; j++) s_[nt][j] = 0.0f;

#pragma unroll
        for (int ks = 0; ks < 8; ks++) {
#pragma unroll
            for (int nt = 0; nt < 4; nt++) {
                uint32_t b[2];
                const uint32_t* kr = &Ks[(nt * 8 + g) * QPT + ks * 8];
                b[0] = kr[t];
                b[1] = kr[t + 4];
                mma_tf32(s_[nt], qa[ks], b);
            }
        }

        const bool masked = (tt >= 2 * rb);
        const int cbase = tt * 32 + 2 * t;
        float mx0 = -INFINITY, mx1 = -INFINITY;
#pragma unroll
        for (int nt = 0; nt < 4; nt++) {
#pragma unroll
            for (int j = 0; j < 4; j++) {
                float v = s_[nt][j] * scale;
                const int col = cbase + nt * 8 + (j & 1);
                const int row = row0 + (j >> 1) * 8;
                if (masked && col > row) v = -INFINITY;
                s_[nt][j] = v;
                if (j < 2) mx0 = fmaxf(mx0, v);
                else mx1 = fmaxf(mx1, v);
            }
        }
        mx0 = fmaxf(mx0, __shfl_xor_sync(0xFFFFFFFFu, mx0, 1));
        mx0 = fmaxf(mx0, __shfl_xor_sync(0xFFFFFFFFu, mx0, 2));
        mx1 = fmaxf(mx1, __shfl_xor_sync(0xFFFFFFFFu, mx1, 1));
        mx1 = fmaxf(mx1, __shfl_xor_sync(0xFFFFFFFFu, mx1, 2));

        const float mn0 = fmaxf(m0, mx0);
        const float mn1 = fmaxf(m1, mx1);
        const float scl0 = __expf(m0 - mn0);
        const float scl1 = __expf(m1 - mn1);

        float rs0 = 0.0f, rs1 = 0.0f;
#pragma unroll
        for (int nt = 0; nt < 4; nt++) {
            float p0 = __expf(s_[nt][0] - mn0);
            float p1 = __expf(s_[nt][1] - mn0);
            float p2 = __expf(s_[nt][2] - mn1);
            float p3 = __expf(s_[nt][3] - mn1);
            rs0 += p0 + p1;
            rs1 += p2 + p3;
            uint32_t* pr = &Ps[(warp * 16 + g) * PPT + nt * 8 + 2 * t];
            *(uint2*)pr = make_uint2(f2tf32(p0), f2tf32(p1));
            *(uint2*)(pr + 8 * PPT) = make_uint2(f2tf32(p2), f2tf32(p3));
        }
        rs0 += __shfl_xor_sync(0xFFFFFFFFu, rs0, 1);
        rs0 += __shfl_xor_sync(0xFFFFFFFFu, rs0, 2);
        rs1 += __shfl_xor_sync(0xFFFFFFFFu, rs1, 1);
        rs1 += __shfl_xor_sync(0xFFFFFFFFu, rs1, 2);

        l0 = l0 * scl0 + rs0;
        l1 = l1 * scl1 + rs1;
        m0 = mn0;
        m1 = mn1;

#pragma unroll
        for (int nt = 0; nt < 8; nt++) {
            o[nt][0] *= scl0;
            o[nt][1] *= scl0;
            o[nt][2] *= scl1;
            o[nt][3] *= scl1;
        }
        __syncwarp();

#pragma unroll
        for (int ks = 0; ks < 4; ks++) {
            uint32_t a[4];
            const uint32_t* pr = &Ps[(warp * 16 + g) * PPT + ks * 8];
            a[0] = pr[t];
            a[1] = pr[8 * PPT + t];
            a[2] = pr[t + 4];
            a[3] = pr[8 * PPT + t + 4];
#pragma unroll
            for (int nt = 0; nt < 8; nt++) {
                uint32_t b[2];
                b[0] = Vs[(ks * 8 + t) * VPT + nt * 8 + g];
                b[1] = Vs[(ks * 8 + t + 4) * VPT + nt * 8 + g];
                mma_tf32(o[nt], a, b);
            }
        }
        __syncwarp();
    }

    const int bb = bh >> 4, hh = bh & 15;
    const float inv0 = 1.0f / l0;
    const float inv1 = 1.0f / l1;
    float* base0 = g_attn + ((size_t)(bb * SEQ + row0)) * DMODEL + hh * 64;
    float* base1 = base0 + (size_t)8 * DMODEL;
#pragma unroll
    for (int nt = 0; nt < 8; nt++) {
        const int c = nt * 8 + 2 * t;
        *(float2*)(base0 + c) = make_float2(o[nt][0] * inv0, o[nt][1] * inv0);
        *(float2*)(base1 + c) = make_float2(o[nt][2] * inv1, o[nt][3] * inv1);
    }
}

// ============================================================
// Launch: kernel launches ONLY
// ============================================================
extern "C" void kernel_launch(void* const* d_in, const int* in_sizes, int n_in,
                              void* d_out, int out_size) {
    const float* x = (const float*)d_in[0];
    const float* wq = (const float*)d_in[1];
    const float* wk = (const float*)d_in[2];
    const float* wv = (const float*)d_in[3];
    const float* wo = (const float*)d_in[4];
    float* out = (float*)d_out;

    dim3 qk_grid(DMODEL / 128, MTOT / 128, 2);  // (8, 32, 2): Q and K fused
    qk3_gemm<<<qk_grid, 256>>>(x, wq, wk);

    dim3 gemm_grid(DMODEL / 128, MTOT / 128);  // (8, 32)
    tf32_gemm<2><<<gemm_grid, 256>>>(x, wv, nullptr);  // V (tf32 TC)

    dim3 attn_grid(SEQ / 64, BHTOT);  // (32, 32)
    flash_attn_tc<<<attn_grid, 128>>>();

    tf32_gemm<3><<<gemm_grid, 256>>>(nullptr, wo, out);  // O (tf32 TC)
}